// round 15
// baseline (speedup 1.0000x reference)
#include <cuda_runtime.h>
#include <cuda_bf16.h>

#define U_NUM 100000
#define I_NUM 50000
#define NN (U_NUM + I_NUM)
#define D 64
#define NE (NN * D)              // 9,600,000 floats per buffer
#define NNZ_MAX 2400000
#define SCAN_NB ((NN + 255) / 256)   // 586 blocks

#define RPB 128                  // rows per fused block
#define SZ_STRIDE 68             // padded row stride in smem (floats)

typedef unsigned long long u64;

// scratch (device globals; only referenced from device code)
__device__ float g_egoA[NE];
__device__ float g_egoB[NE];
__device__ float g_sum[NE];
__device__ int   g_cnt[NN];          // per-row degree
__device__ int   g_rowptr[NN + 1];   // CSR row pointers
__device__ int   g_cursor[NN];       // scatter cursors
__device__ int2  g_cv[NNZ_MAX];      // (col, val bits) row-sorted
__device__ int   g_blksum[1024];     // scan partials

// ---------------------------------------------------------------------------
// packed f32x2 helpers (FFMA2 is PTX-only; ptxas never auto-fuses)
// ---------------------------------------------------------------------------
__device__ __forceinline__ u64 pack2(float x) {
    u64 r; asm("mov.b64 %0, {%1, %1};" : "=l"(r) : "f"(x)); return r;
}
__device__ __forceinline__ u64 fma2(u64 a, u64 b, u64 c) {
    u64 d; asm("fma.rn.f32x2 %0, %1, %2, %3;" : "=l"(d) : "l"(a), "l"(b), "l"(c));
    return d;
}
__device__ __forceinline__ float2 unpack2(u64 v) {
    float2 f; asm("mov.b64 {%0, %1}, %2;" : "=f"(f.x), "=f"(f.y) : "l"(v));
    return f;
}
__device__ __forceinline__ float comp4(const float4& v, int q) {
    return (q == 0) ? v.x : (q == 1) ? v.y : (q == 2) ? v.z : v.w;
}

// ---------------------------------------------------------------------------
// init: egoA = concat(user, item); sum = egoA; cnt = 0
// ---------------------------------------------------------------------------
__global__ void init_k(const float* __restrict__ u, const float* __restrict__ it) {
    int i = blockIdx.x * blockDim.x + threadIdx.x;   // float4 index
    const int n4 = NE / 4;
    if (i < NN) g_cnt[i] = 0;
    if (i >= n4) return;
    const int un4 = U_NUM * D / 4;
    float4 v = (i < un4) ? ((const float4*)u)[i] : ((const float4*)it)[i - un4];
    ((float4*)g_egoA)[i] = v;
    ((float4*)g_sum)[i] = v;
}

// ---------------------------------------------------------------------------
// CSR build: histogram -> exclusive scan (3 kernels) -> scatter
// ---------------------------------------------------------------------------
__global__ void hist_k(const int* __restrict__ rows, int nnz) {
    int e = blockIdx.x * blockDim.x + threadIdx.x;
    if (e < nnz) atomicAdd(&g_cnt[rows[e]], 1);
}

__global__ void scan1_k() {
    __shared__ int s[256];
    const int t = threadIdx.x;
    const int idx = blockIdx.x * 256 + t;
    int x = (idx < NN) ? g_cnt[idx] : 0;
    s[t] = x;
    __syncthreads();
#pragma unroll
    for (int off = 1; off < 256; off <<= 1) {
        int y = (t >= off) ? s[t - off] : 0;
        __syncthreads();
        s[t] += y;
        __syncthreads();
    }
    if (idx < NN) g_rowptr[idx] = s[t] - x;
    if (t == 255) g_blksum[blockIdx.x] = s[255];
}

__global__ void scan2_k() {
    __shared__ int s[1024];
    const int t = threadIdx.x;
    int x = (t < SCAN_NB) ? g_blksum[t] : 0;
    s[t] = x;
    __syncthreads();
#pragma unroll
    for (int off = 1; off < 1024; off <<= 1) {
        int y = (t >= off) ? s[t - off] : 0;
        __syncthreads();
        s[t] += y;
        __syncthreads();
    }
    if (t < SCAN_NB) g_blksum[t] = s[t] - x;
}

__global__ void scan3_k(int nnz) {
    const int idx = blockIdx.x * 256 + threadIdx.x;
    if (idx < NN) {
        int v = g_rowptr[idx] + g_blksum[blockIdx.x];
        g_rowptr[idx] = v;
        g_cursor[idx] = v;
    }
    if (idx == 0) g_rowptr[NN] = nnz;
}

__global__ void scatter_k(const int* __restrict__ rows, const int* __restrict__ cols,
                          const float* __restrict__ vals, int nnz) {
    int e = blockIdx.x * blockDim.x + threadIdx.x;
    if (e >= nnz) return;
    const int r = rows[e];
    const int pos = atomicAdd(&g_cursor[r], 1);
    g_cv[pos] = make_int2(cols[e], __float_as_int(vals[e]));
}

// ---------------------------------------------------------------------------
// fused layer kernel:
//   phase 1: CSR gather for RPB rows -> s = agg+ego, z = agg*ego into smem
//   phase 2: ego_out = lrelu(s @ w1 + z @ w2); sum += ; out on last layer
// parity selects ego_in / ego_out buffers (double buffering kills the
// cross-block read/write hazard).
// dynamic smem: [w1s 4096][w2s 4096][s RPB*68][z RPB*68] floats = 100 KB
// ---------------------------------------------------------------------------
__global__ __launch_bounds__(256, 2)
void fused_k(const float* __restrict__ w1, const float* __restrict__ w2,
             float* __restrict__ out, int parity, int last) {
    extern __shared__ float smem[];
    float* w1s = smem;
    float* w2s = smem + 4096;
    float* ss  = smem + 8192;
    float* zs  = smem + 8192 + RPB * SZ_STRIDE;

    const float* ein  = parity ? g_egoB : g_egoA;
    float*       eout = parity ? g_egoA : g_egoB;

    const int tid  = threadIdx.x;
    const int base = blockIdx.x * RPB;

    // load both weight matrices (coalesced float4)
#pragma unroll
    for (int i = 0; i < 4; i++) {
        ((float4*)w1s)[tid + i * 256] = ((const float4*)w1)[tid + i * 256];
        ((float4*)w2s)[tid + i * 256] = ((const float4*)w2)[tid + i * 256];
    }

    // ---------------- phase 1: gather ----------------
    // 16 threads per node; 16 nodes per pass; 8 passes cover RPB=128 rows
#pragma unroll
    for (int p = 0; p < 8; p++) {
        const int task  = p * 256 + tid;
        const int lnode = task >> 4;
        const int node  = base + lnode;
        const int part  = (task & 15) * 4;
        if (node < NN) {
            const int beg = __ldg(&g_rowptr[node]);
            const int end = __ldg(&g_rowptr[node + 1]);
            float4 acc = make_float4(0.f, 0.f, 0.f, 0.f);
            int i = beg;
            for (; i + 4 <= end; i += 4) {
                int2 c0 = __ldg(&g_cv[i]);
                int2 c1 = __ldg(&g_cv[i + 1]);
                int2 c2 = __ldg(&g_cv[i + 2]);
                int2 c3 = __ldg(&g_cv[i + 3]);
                float4 e0 = *(const float4*)(ein + (size_t)c0.x * D + part);
                float4 e1 = *(const float4*)(ein + (size_t)c1.x * D + part);
                float4 e2 = *(const float4*)(ein + (size_t)c2.x * D + part);
                float4 e3 = *(const float4*)(ein + (size_t)c3.x * D + part);
                float v0 = __int_as_float(c0.y), v1 = __int_as_float(c1.y);
                float v2 = __int_as_float(c2.y), v3 = __int_as_float(c3.y);
                acc.x += v0 * e0.x; acc.y += v0 * e0.y; acc.z += v0 * e0.z; acc.w += v0 * e0.w;
                acc.x += v1 * e1.x; acc.y += v1 * e1.y; acc.z += v1 * e1.z; acc.w += v1 * e1.w;
                acc.x += v2 * e2.x; acc.y += v2 * e2.y; acc.z += v2 * e2.z; acc.w += v2 * e2.w;
                acc.x += v3 * e3.x; acc.y += v3 * e3.y; acc.z += v3 * e3.z; acc.w += v3 * e3.w;
            }
            for (; i < end; i++) {
                int2 cv = __ldg(&g_cv[i]);
                float4 e = *(const float4*)(ein + (size_t)cv.x * D + part);
                float v = __int_as_float(cv.y);
                acc.x += v * e.x; acc.y += v * e.y; acc.z += v * e.z; acc.w += v * e.w;
            }
            float4 e = *(const float4*)(ein + (size_t)node * D + part);
            float4 sv = make_float4(acc.x + e.x, acc.y + e.y, acc.z + e.z, acc.w + e.w);
            float4 zv = make_float4(acc.x * e.x, acc.y * e.y, acc.z * e.z, acc.w * e.w);
            *(float4*)(ss + lnode * SZ_STRIDE + part) = sv;
            *(float4*)(zs + lnode * SZ_STRIDE + part) = zv;
        }
    }
    __syncthreads();

    // ---------------- phase 2: dual GEMM from smem ----------------
    const int lrow = tid >> 2;          // 0..63 -> 2 rows each
    const int cg   = (tid & 3) * 16;    // output col group

    u64 acc2[2][8];
    const u64 z64 = pack2(0.f);
#pragma unroll
    for (int j = 0; j < 2; j++)
#pragma unroll
        for (int p = 0; p < 8; p++) acc2[j][p] = z64;

#pragma unroll 4
    for (int k4 = 0; k4 < 16; k4++) {
        float4 s4[2], z4[2];
#pragma unroll
        for (int j = 0; j < 2; j++) {
            const int ln = lrow * 2 + j;
            s4[j] = *(const float4*)(ss + ln * SZ_STRIDE + k4 * 4);
            z4[j] = *(const float4*)(zs + ln * SZ_STRIDE + k4 * 4);
        }
#pragma unroll
        for (int q = 0; q < 4; q++) {
            const ulonglong2* w1p = (const ulonglong2*)(w1s + (k4 * 4 + q) * 64 + cg);
            const ulonglong2* w2p = (const ulonglong2*)(w2s + (k4 * 4 + q) * 64 + cg);
            ulonglong2 A0 = w1p[0], A1 = w1p[1], A2 = w1p[2], A3 = w1p[3];
            ulonglong2 B0 = w2p[0], B1 = w2p[1], B2 = w2p[2], B3 = w2p[3];
#pragma unroll
            for (int j = 0; j < 2; j++) {
                const u64 s2 = pack2(comp4(s4[j], q));
                const u64 zz = pack2(comp4(z4[j], q));
                acc2[j][0] = fma2(s2, A0.x, acc2[j][0]);
                acc2[j][0] = fma2(zz, B0.x, acc2[j][0]);
                acc2[j][1] = fma2(s2, A0.y, acc2[j][1]);
                acc2[j][1] = fma2(zz, B0.y, acc2[j][1]);
                acc2[j][2] = fma2(s2, A1.x, acc2[j][2]);
                acc2[j][2] = fma2(zz, B1.x, acc2[j][2]);
                acc2[j][3] = fma2(s2, A1.y, acc2[j][3]);
                acc2[j][3] = fma2(zz, B1.y, acc2[j][3]);
                acc2[j][4] = fma2(s2, A2.x, acc2[j][4]);
                acc2[j][4] = fma2(zz, B2.x, acc2[j][4]);
                acc2[j][5] = fma2(s2, A2.y, acc2[j][5]);
                acc2[j][5] = fma2(zz, B2.y, acc2[j][5]);
                acc2[j][6] = fma2(s2, A3.x, acc2[j][6]);
                acc2[j][6] = fma2(zz, B3.x, acc2[j][6]);
                acc2[j][7] = fma2(s2, A3.y, acc2[j][7]);
                acc2[j][7] = fma2(zz, B3.y, acc2[j][7]);
            }
        }
    }

    // epilogue
#pragma unroll
    for (int j = 0; j < 2; j++) {
        const int r = base + lrow * 2 + j;
        if (r >= NN) continue;
        const size_t addr = (size_t)r * D + cg;
#pragma unroll
        for (int i = 0; i < 4; i++) {
            float2 lo = unpack2(acc2[j][i * 2]);
            float2 hi = unpack2(acc2[j][i * 2 + 1]);
            float4 e;
            e.x = lo.x; e.y = lo.y; e.z = hi.x; e.w = hi.y;
            e.x = (e.x > 0.f) ? e.x : 0.01f * e.x;
            e.y = (e.y > 0.f) ? e.y : 0.01f * e.y;
            e.z = (e.z > 0.f) ? e.z : 0.01f * e.z;
            e.w = (e.w > 0.f) ? e.w : 0.01f * e.w;
            *(float4*)(eout + addr + i * 4) = e;

            float4 s = *(const float4*)(g_sum + addr + i * 4);
            s.x += e.x; s.y += e.y; s.z += e.z; s.w += e.w;
            *(float4*)(g_sum + addr + i * 4) = s;

            if (last) {
                *(float4*)(out + addr + i * 4) =
                    make_float4(s.x * 0.25f, s.y * 0.25f, s.z * 0.25f, s.w * 0.25f);
            }
        }
    }
}

// ---------------------------------------------------------------------------
extern "C" void kernel_launch(void* const* d_in, const int* in_sizes, int n_in,
                              void* d_out, int out_size) {
    const float* user = (const float*)d_in[0];
    const float* item = (const float*)d_in[1];
    const float* w1   = (const float*)d_in[2];   // [3,64,64]
    const float* w2   = (const float*)d_in[3];   // [3,64,64]
    const float* vals = (const float*)d_in[4];
    const int*   rows = (const int*)d_in[5];
    const int*   cols = (const int*)d_in[6];
    float* out = (float*)d_out;
    const int nnz = in_sizes[4];

    const int n4 = NE / 4;
    const int gb_elem  = (n4 + 255) / 256;
    const int gb_edge  = (nnz + 255) / 256;
    const int gb_fused = (NN + RPB - 1) / RPB;

    const int smem_bytes = (8192 + 2 * RPB * SZ_STRIDE) * 4;   // 100 KB
    // Unconditional (no static guard — harness forbids state). Idempotent,
    // not a stream op, so graph capture is unaffected.
    cudaFuncSetAttribute(fused_k, cudaFuncAttributeMaxDynamicSharedMemorySize,
                         smem_bytes);

    init_k<<<gb_elem, 256>>>(user, item);

    // CSR build (amortized over 3 layers)
    hist_k<<<gb_edge, 256>>>(rows, nnz);
    scan1_k<<<SCAN_NB, 256>>>();
    scan2_k<<<1, 1024>>>();
    scan3_k<<<SCAN_NB, 256>>>(nnz);
    scatter_k<<<gb_edge, 256>>>(rows, cols, vals, nnz);

    for (int k = 0; k < 3; k++) {
        fused_k<<<gb_fused, 256, smem_bytes>>>(w1 + k * 64 * 64, w2 + k * 64 * 64,
                                               out, k & 1, (k == 2) ? 1 : 0);
    }
}